// round 2
// baseline (speedup 1.0000x reference)
#include <cuda_runtime.h>
#include <cuda_bf16.h>
#include <cstdint>

// ---------------- problem constants ----------------
#define B   64
#define T   400
#define H   256
#define E   128
#define V   50000
#define X   500
#define H2  512        // 2H
#define VX  50500      // V + X

// output tuple offsets (floats)
#define OFF_FINAL 0
#define OFF_HS    (B*VX)                  // 3,232,000
#define OFF_CS    (OFF_HS + B*H)
#define OFF_CT    (OFF_CS + B*H)
#define OFF_ATTN  (OFF_CT + B*H2)
#define OFF_PGEN  (OFF_ATTN + B*T)
#define OFF_COV   (OFF_PGEN + B)
#define OUT_TOTAL (OFF_COV + B*T)         // 3,348,800

// ---------------- device scratch (no allocations allowed) ----------------
__device__ float g_xin[B*640];        // [c_t_1 | y_emb]
__device__ float g_x[B*E];            // x_context output
__device__ float g_gates[B*4*H];      // LSTM gates
__device__ float g_sthat[B*H2];       // [h_s | c_s]
__device__ float g_decfea[B*H2];
__device__ float g_scores[B*T];
__device__ float g_attn[B*T];
__device__ float g_ct[B*H2];
__device__ float g_cat1152[B*1152];   // [c_t | s_t_hat | x]
__device__ float g_cat768[B*768];     // [h_s | c_t]
__device__ float g_outvec[B*H];
__device__ float g_rowsum[B];
__device__ float g_pgen[B];
__device__ float g_scale[B];

// buffer selectors for the templated GEMM (resolved in DEVICE code — passing
// __device__ symbols as host-side kernel args is invalid and was the R1 bug)
#define SEL_EXT    (-1)
#define SEL_XIN      0
#define SEL_X        1
#define SEL_STHAT    2
#define SEL_CAT768   3
#define SEL_GATES    4
#define SEL_DECFEA   5
#define SEL_OUTVEC   6

// ---------------- math helpers ----------------
__device__ __forceinline__ float ftanh(float x) {
    x = fminf(fmaxf(x, -15.f), 15.f);
    float e = __expf(2.f * x);
    return __fdividef(e - 1.f, e + 1.f);
}
__device__ __forceinline__ float fsig(float x) {
    return __fdividef(1.f, 1.f + __expf(-x));
}

// ---------------- K1a: build xin = [c_t_1 | embedding[y]] ----------------
__global__ void __launch_bounds__(128) xin_kernel(const int* __restrict__ y,
                           const float* __restrict__ ct1,
                           const float* __restrict__ emb) {
    int b = blockIdx.x;
    int yi = y[b];
    for (int k = threadIdx.x; k < 640; k += blockDim.x)
        g_xin[b*640 + k] = (k < H2) ? ct1[b*H2 + k] : emb[(size_t)yi*E + (k - H2)];
}

// ---------------- generic small GEMM: C[64,N] = A[64,K] @ W[N,K]^T (+bias) ----------------
// 64xN output; block covers 64 rows x 64 cols. 256 threads, 4x4 microtile.
template<int ASEL, int CSEL, int ACC>
__global__ void __launch_bounds__(256) gemm64(const float* __restrict__ Aext,
                       const float* __restrict__ W,
                       const float* __restrict__ b1, const float* __restrict__ b2,
                       int K, int N) {
    const float* A =
        (ASEL == SEL_XIN)    ? g_xin :
        (ASEL == SEL_X)      ? g_x :
        (ASEL == SEL_STHAT)  ? g_sthat :
        (ASEL == SEL_CAT768) ? g_cat768 : Aext;
    float* C =
        (CSEL == SEL_X)      ? g_x :
        (CSEL == SEL_GATES)  ? g_gates :
        (CSEL == SEL_DECFEA) ? g_decfea : g_outvec;

    const int tid = threadIdx.x;
    const int tr = tid >> 4;          // 0..15 -> m group
    const int tc = tid & 15;          // 0..15 -> n group
    const int n0blk = blockIdx.x * 64;
    __shared__ float As[32 * 65];     // [kk][m]
    __shared__ float Ws[32 * 65];     // [kk][n]
    float accv[4][4];
    #pragma unroll
    for (int i = 0; i < 4; i++)
        #pragma unroll
        for (int j = 0; j < 4; j++) accv[i][j] = 0.f;

    for (int k0 = 0; k0 < K; k0 += 32) {
        for (int i = tid; i < 64*32; i += 256) {
            int m = i >> 5, kk = i & 31;
            As[kk*65 + m] = A[m*K + k0 + kk];
        }
        for (int i = tid; i < 64*32; i += 256) {
            int n = i >> 5, kk = i & 31;
            int ng = n0blk + n;
            Ws[kk*65 + n] = (ng < N) ? W[(size_t)ng*K + k0 + kk] : 0.f;
        }
        __syncthreads();
        #pragma unroll
        for (int kk = 0; kk < 32; kk++) {
            float a[4], w[4];
            #pragma unroll
            for (int i = 0; i < 4; i++) a[i] = As[kk*65 + tr*4 + i];
            #pragma unroll
            for (int j = 0; j < 4; j++) w[j] = Ws[kk*65 + tc*4 + j];
            #pragma unroll
            for (int i = 0; i < 4; i++)
                #pragma unroll
                for (int j = 0; j < 4; j++) accv[i][j] = fmaf(a[i], w[j], accv[i][j]);
        }
        __syncthreads();
    }
    #pragma unroll
    for (int i = 0; i < 4; i++) {
        int m = tr*4 + i;
        #pragma unroll
        for (int j = 0; j < 4; j++) {
            int ng = n0blk + tc*4 + j;
            if (ng < N) {
                float v = accv[i][j];
                if (b1) v += b1[ng];
                if (b2) v += b2[ng];
                if (ACC) C[m*N + ng] += v;
                else     C[m*N + ng]  = v;
            }
        }
    }
}

// ---------------- K3: LSTM cell elementwise ----------------
__global__ void __launch_bounds__(H) lstm_kernel(const float* __restrict__ c0) {
    int b = blockIdx.x, h = threadIdx.x;
    const float* g = g_gates + b*4*H;
    float ig = fsig(g[h]);
    float fg = fsig(g[H + h]);
    float gg = ftanh(g[2*H + h]);
    float og = fsig(g[3*H + h]);
    float cs = fg * c0[b*H + h] + ig * gg;
    float hs = og * ftanh(cs);
    g_sthat[b*H2 + h]       = hs;
    g_sthat[b*H2 + H + h]   = cs;
}

// ---------------- K5: attention scores (52 MB stream) ----------------
__global__ void __launch_bounds__(256) attn_scores_kernel(const float* __restrict__ ef,
                                   const float* __restrict__ Wv) {
    int warp = (blockIdx.x * blockDim.x + threadIdx.x) >> 5;
    int lane = threadIdx.x & 31;
    if (warp >= B*T) return;
    int b = warp / T;
    const float4* e4 = (const float4*)(ef + (size_t)warp * H2);
    const float4* d4 = (const float4*)(g_decfea + b * H2);
    const float4* w4 = (const float4*)Wv;
    float acc = 0.f;
    #pragma unroll
    for (int i = 0; i < 4; i++) {
        int p = i*32 + lane;
        float4 a = e4[p], d = d4[p], w = w4[p];
        acc += ftanh(a.x + d.x) * w.x;
        acc += ftanh(a.y + d.y) * w.y;
        acc += ftanh(a.z + d.z) * w.z;
        acc += ftanh(a.w + d.w) * w.w;
    }
    #pragma unroll
    for (int s = 16; s > 0; s >>= 1) acc += __shfl_xor_sync(0xFFFFFFFFu, acc, s);
    if (lane == 0) g_scores[warp] = acc;
}

// ---------------- K6: softmax over T + mask/renorm/stmt; zero g_ct/g_rowsum ----------------
__global__ void __launch_bounds__(256) softmaxT_kernel(const float* __restrict__ mask,
                                const float* __restrict__ stmt) {
    int b = blockIdx.x, tid = threadIdx.x;
    __shared__ float red[256];
    bool v0 = tid < T;
    bool v1 = (tid + 256) < T;
    float s0 = v0 ? g_scores[b*T + tid]       : -1e30f;
    float s1 = v1 ? g_scores[b*T + tid + 256] : -1e30f;

    // max
    red[tid] = fmaxf(s0, s1); __syncthreads();
    for (int s = 128; s > 0; s >>= 1) { if (tid < s) red[tid] = fmaxf(red[tid], red[tid+s]); __syncthreads(); }
    float M = red[0]; __syncthreads();

    float e0 = v0 ? __expf(s0 - M) : 0.f;
    float e1 = v1 ? __expf(s1 - M) : 0.f;
    red[tid] = e0 + e1; __syncthreads();
    for (int s = 128; s > 0; s >>= 1) { if (tid < s) red[tid] += red[tid+s]; __syncthreads(); }
    float S = red[0]; __syncthreads();

    float m0 = v0 ? mask[b*T + tid]       : 0.f;
    float m1 = v1 ? mask[b*T + tid + 256] : 0.f;
    float a0 = __fdividef(e0, S) * m0;
    float a1 = __fdividef(e1, S) * m1;
    red[tid] = a0 + a1; __syncthreads();
    for (int s = 128; s > 0; s >>= 1) { if (tid < s) red[tid] += red[tid+s]; __syncthreads(); }
    float S2 = red[0]; __syncthreads();

    if (v0) g_attn[b*T + tid]       = __fdividef(a0, S2) + (stmt[b*T + tid]       * m0);
    if (v1) g_attn[b*T + tid + 256] = __fdividef(a1, S2) + (stmt[b*T + tid + 256] * m1);

    // zero c_t accumulator and rowsum
    g_ct[b*H2 + tid]       = 0.f;
    g_ct[b*H2 + tid + 256] = 0.f;
    if (tid == 0) g_rowsum[b] = 0.f;
}

// ---------------- K7: c_t = attn @ encoder_outputs (52 MB stream) ----------------
__global__ void __launch_bounds__(256) ct_kernel(const float* __restrict__ eo) {
    int b = blockIdx.x, z = blockIdx.y;   // z in 0..7, 50 timesteps each
    int tid = threadIdx.x;
    __shared__ float sa[50];
    if (tid < 50) sa[tid] = g_attn[b*T + z*50 + tid];
    __syncthreads();
    const float* base = eo + ((size_t)b*T + z*50) * H2;
    float acc0 = 0.f, acc1 = 0.f;
    #pragma unroll 5
    for (int t = 0; t < 50; t++) {
        float a = sa[t];
        acc0 = fmaf(a, base[t*H2 + tid],       acc0);
        acc1 = fmaf(a, base[t*H2 + tid + 256], acc1);
    }
    atomicAdd(&g_ct[b*H2 + tid],       acc0);
    atomicAdd(&g_ct[b*H2 + tid + 256], acc1);
}

// ---------------- K8a: concat buffers ----------------
__global__ void __launch_bounds__(256) cats_kernel() {
    int b = blockIdx.x;
    for (int k = threadIdx.x; k < 1152; k += blockDim.x) {
        float v;
        if (k < 512)       v = g_ct[b*H2 + k];
        else if (k < 1024) v = g_sthat[b*H2 + (k - 512)];
        else               v = g_x[b*E + (k - 1024)];
        g_cat1152[b*1152 + k] = v;
    }
    for (int k = threadIdx.x; k < 768; k += blockDim.x) {
        float v = (k < 256) ? g_sthat[b*H2 + k] : g_ct[b*H2 + (k - 256)];
        g_cat768[b*768 + k] = v;
    }
}

// ---------------- K8b: p_gen ----------------
__global__ void __launch_bounds__(128) pgen_kernel(const float* __restrict__ Wpg,
                                                   const float* __restrict__ bpg) {
    int b = blockIdx.x, tid = threadIdx.x;
    __shared__ float red[128];
    float acc = 0.f;
    for (int k = tid; k < 1152; k += 128)
        acc = fmaf(g_cat1152[b*1152 + k], Wpg[k], acc);
    red[tid] = acc; __syncthreads();
    for (int s = 64; s > 0; s >>= 1) { if (tid < s) red[tid] += red[tid+s]; __syncthreads(); }
    if (tid == 0) g_pgen[b] = fsig(red[0] + bpg[0]);
}

// ---------------- K10: vocab GEMM + exp + rowsum (51 MB stream) ----------------
// BN=128 cols per block, 256 threads, 4x8 microtile. K = 256.
__global__ void __launch_bounds__(256) vocab_kernel(const float* __restrict__ Wo2,
                             const float* __restrict__ bo2,
                             float* __restrict__ outF) {
    const int tid = threadIdx.x;
    const int tr = tid >> 4;          // 0..15
    const int tc = tid & 15;          // 0..15
    const int n0blk = blockIdx.x * 128;
    __shared__ float As[32 * 65];     // [kk][m]
    __shared__ float Ws[32 * 129];    // [kk][n]
    __shared__ float srow[B];
    float accv[4][8];
    #pragma unroll
    for (int i = 0; i < 4; i++)
        #pragma unroll
        for (int j = 0; j < 8; j++) accv[i][j] = 0.f;

    for (int k0 = 0; k0 < H; k0 += 32) {
        for (int i = tid; i < 64*32; i += 256) {
            int m = i >> 5, kk = i & 31;
            As[kk*65 + m] = g_outvec[m*H + k0 + kk];
        }
        for (int i = tid; i < 128*32; i += 256) {
            int n = i >> 5, kk = i & 31;
            int ng = n0blk + n;
            Ws[kk*129 + n] = (ng < V) ? Wo2[(size_t)ng*H + k0 + kk] : 0.f;
        }
        __syncthreads();
        #pragma unroll
        for (int kk = 0; kk < 32; kk++) {
            float a[4], w[8];
            #pragma unroll
            for (int i = 0; i < 4; i++) a[i] = As[kk*65 + tr*4 + i];
            #pragma unroll
            for (int j = 0; j < 8; j++) w[j] = Ws[kk*129 + tc*8 + j];
            #pragma unroll
            for (int i = 0; i < 4; i++)
                #pragma unroll
                for (int j = 0; j < 8; j++) accv[i][j] = fmaf(a[i], w[j], accv[i][j]);
        }
        __syncthreads();
    }

    if (tid < B) srow[tid] = 0.f;
    __syncthreads();
    #pragma unroll
    for (int i = 0; i < 4; i++) {
        int m = tr*4 + i;
        float rs = 0.f;
        #pragma unroll
        for (int j = 0; j < 8; j++) {
            int ng = n0blk + tc*8 + j;
            if (ng < V) {
                float e = __expf(accv[i][j] + bo2[ng]);
                outF[(size_t)m*VX + ng] = e;
                rs += e;
            }
        }
        atomicAdd(&srow[m], rs);
    }
    __syncthreads();
    if (tid < B) atomicAdd(&g_rowsum[tid], srow[tid]);
}

// ---------------- K10b: scale = pgen / rowsum ----------------
__global__ void __launch_bounds__(64) scale_kernel() {
    int t = threadIdx.x;
    if (t < B) g_scale[t] = g_pgen[t] / g_rowsum[t];
}

// ---------------- K11a: normalize + extras + aux-output copies ----------------
__global__ void __launch_bounds__(256) finalize_kernel(float* __restrict__ out,
                                const float* __restrict__ extra,
                                const float* __restrict__ cov,
                                int full) {
    const int totalV = B * VX;
    const int extraN = full ? (B*H + B*H + B*H2 + B*T + B + B*T) : 0;
    const int total  = totalV + extraN;
    for (int idx = blockIdx.x * blockDim.x + threadIdx.x; idx < total;
         idx += gridDim.x * blockDim.x) {
        if (idx < totalV) {
            int b = idx / VX;
            int v = idx - b * VX;
            if (v < V) out[idx] = out[idx] * g_scale[b];
            else       out[idx] = extra[b*X + (v - V)];
        } else {
            int r = idx - totalV;
            if (r < B*H) {                                   // h_s
                int b = r / H, h = r - b*H;
                out[OFF_HS + r] = g_sthat[b*H2 + h];
            } else if ((r -= B*H) < B*H) {                   // c_s
                int b = r / H, h = r - b*H;
                out[OFF_CS + r] = g_sthat[b*H2 + H + h];
            } else if ((r -= B*H) < B*H2) {                  // c_t
                out[OFF_CT + r] = g_ct[r];
            } else if ((r -= B*H2) < B*T) {                  // attn
                out[OFF_ATTN + r] = g_attn[r];
            } else if ((r -= B*T) < B) {                     // p_gen
                out[OFF_PGEN + r] = g_pgen[r];
            } else {                                         // coverage
                r -= B;
                out[OFF_COV + r] = cov[r];
            }
        }
    }
}

// ---------------- K11b: pointer scatter ----------------
__global__ void __launch_bounds__(256) scatter_kernel(float* __restrict__ out,
                                                      const int* __restrict__ ebev) {
    int idx = blockIdx.x * blockDim.x + threadIdx.x;
    if (idx >= B*T) return;
    int b = idx / T;
    float v = (1.f - g_pgen[b]) * g_attn[idx];
    int col = ebev[idx];
    atomicAdd(&out[(size_t)b*VX + col], v);
}

// ---------------- host launcher ----------------
extern "C" void kernel_launch(void* const* d_in, const int* in_sizes, int n_in,
                              void* d_out, int out_size) {
    const int*   y     = (const int*)  d_in[0];
    const float* h0    = (const float*)d_in[1];
    // d_in[2] = c0 (used below)
    const float* c0    = (const float*)d_in[2];
    const float* eo    = (const float*)d_in[3];
    const float* ef    = (const float*)d_in[4];
    const float* stmt  = (const float*)d_in[5];
    const float* mask  = (const float*)d_in[6];
    const float* ct1   = (const float*)d_in[7];
    const float* extra = (const float*)d_in[8];
    const int*   ebev  = (const int*)  d_in[9];
    const float* cov   = (const float*)d_in[10];
    // optional "step" scalar at index 11
    int p = (n_in > 11 && in_sizes[11] == 1) ? 12 : 11;
    const float* emb  = (const float*)d_in[p+0];
    const float* Wxc  = (const float*)d_in[p+1];
    const float* bxc  = (const float*)d_in[p+2];
    const float* W_ih = (const float*)d_in[p+3];
    const float* W_hh = (const float*)d_in[p+4];
    const float* b_ih = (const float*)d_in[p+5];
    const float* b_hh = (const float*)d_in[p+6];
    const float* Wdp  = (const float*)d_in[p+7];
    const float* bdp  = (const float*)d_in[p+8];
    const float* Wv   = (const float*)d_in[p+9];
    const float* Wpg  = (const float*)d_in[p+10];
    const float* bpg  = (const float*)d_in[p+11];
    const float* Wo1  = (const float*)d_in[p+12];
    const float* bo1  = (const float*)d_in[p+13];
    const float* Wo2  = (const float*)d_in[p+14];
    const float* bo2  = (const float*)d_in[p+15];
    float* out = (float*)d_out;
    int full = (out_size >= OUT_TOTAL) ? 1 : 0;

    // 1. x = [c_t_1 | emb[y]] @ Wxc^T + bxc
    xin_kernel<<<B, 128>>>(y, ct1, emb);
    gemm64<SEL_XIN, SEL_X, 0><<<(E + 63)/64, 256>>>(nullptr, Wxc, bxc, nullptr, 640, E);

    // 2. LSTM gates = x @ W_ih^T + h0 @ W_hh^T + b_ih + b_hh
    gemm64<SEL_X, SEL_GATES, 0><<<(4*H + 63)/64, 256>>>(nullptr, W_ih, b_ih, b_hh, E, 4*H);
    gemm64<SEL_EXT, SEL_GATES, 1><<<(4*H + 63)/64, 256>>>(h0, W_hh, nullptr, nullptr, H, 4*H);
    lstm_kernel<<<B, H>>>(c0);

    // 3. dec_fea = s_t_hat @ Wdp^T + bdp
    gemm64<SEL_STHAT, SEL_DECFEA, 0><<<(H2 + 63)/64, 256>>>(nullptr, Wdp, bdp, nullptr, H2, H2);

    // 4. attention
    attn_scores_kernel<<<(B*T + 7)/8, 256>>>(ef, Wv);
    softmaxT_kernel<<<B, 256>>>(mask, stmt);
    ct_kernel<<<dim3(B, 8), 256>>>(eo);

    // 5. p_gen and output head
    cats_kernel<<<B, 256>>>();
    pgen_kernel<<<B, 128>>>(Wpg, bpg);
    gemm64<SEL_CAT768, SEL_OUTVEC, 0><<<(H + 63)/64, 256>>>(nullptr, Wo1, bo1, nullptr, 768, H);

    // 6. vocab distribution
    vocab_kernel<<<(V + 127)/128, 256>>>(Wo2, bo2, out);
    scale_kernel<<<1, 64>>>();
    finalize_kernel<<<1024, 256>>>(out, extra, cov, full);
    scatter_kernel<<<(B*T + 255)/256, 256>>>(out, ebev);
}

// round 3
// speedup vs baseline: 1.0095x; 1.0095x over previous
#include <cuda_runtime.h>
#include <cuda_bf16.h>
#include <cstdint>

// ---------------- problem constants ----------------
#define B   64
#define T   400
#define H   256
#define E   128
#define V   50000
#define X   500
#define H2  512        // 2H
#define VX  50500      // V + X

// output tuple offsets (floats)
#define OFF_FINAL 0
#define OFF_HS    (B*VX)                  // 3,232,000
#define OFF_CS    (OFF_HS + B*H)
#define OFF_CT    (OFF_CS + B*H)
#define OFF_ATTN  (OFF_CT + B*H2)
#define OFF_PGEN  (OFF_ATTN + B*T)
#define OFF_COV   (OFF_PGEN + B)
#define OUT_TOTAL (OFF_COV + B*T)         // 3,348,800

// ---------------- device scratch (no allocations allowed) ----------------
__device__ float g_xin[B*640];        // [c_t_1 | y_emb]
__device__ float g_x[B*E];            // x_context output
__device__ float g_gates[B*4*H];      // LSTM gates
__device__ float g_sthat[B*H2];       // [h_s | c_s]
__device__ float g_decfea[B*H2];
__device__ float g_scores[B*T];
__device__ float g_attn[B*T];
__device__ float g_ct[B*H2];
__device__ float g_cat1152[B*1152];   // [c_t | s_t_hat | x]
__device__ float g_cat768[B*768];     // [h_s | c_t]
__device__ float g_outvec[B*H];
__device__ float g_rowsum[B];
__device__ float g_pgen[B];
__device__ float g_scale[B];

// buffer selectors for the templated GEMM (resolved in DEVICE code — passing
// __device__ symbols as host-side kernel args is invalid and was the R1 bug)
#define SEL_EXT    (-1)
#define SEL_XIN      0
#define SEL_X        1
#define SEL_STHAT    2
#define SEL_CAT768   3
#define SEL_GATES    4
#define SEL_DECFEA   5
#define SEL_OUTVEC   6

// ---------------- math helpers ----------------
__device__ __forceinline__ float ftanh(float x) {
    x = fminf(fmaxf(x, -15.f), 15.f);
    float e = __expf(2.f * x);
    return __fdividef(e - 1.f, e + 1.f);
}
__device__ __forceinline__ float fsig(float x) {
    return __fdividef(1.f, 1.f + __expf(-x));
}

// ---------------- K1a: build xin = [c_t_1 | embedding[y]] ----------------
__global__ void __launch_bounds__(128) xin_kernel(const int* __restrict__ y,
                           const float* __restrict__ ct1,
                           const float* __restrict__ emb) {
    int b = blockIdx.x;
    int yi = y[b];
    for (int k = threadIdx.x; k < 640; k += blockDim.x)
        g_xin[b*640 + k] = (k < H2) ? ct1[b*H2 + k] : emb[(size_t)yi*E + (k - H2)];
}

// ---------------- generic small GEMM: C[64,N] = A[64,K] @ W[N,K]^T (+bias) ----------------
// 64xN output; block covers 64 rows x 64 cols. 256 threads, 4x4 microtile.
template<int ASEL, int CSEL, int ACC>
__global__ void __launch_bounds__(256) gemm64(const float* __restrict__ Aext,
                       const float* __restrict__ W,
                       const float* __restrict__ b1, const float* __restrict__ b2,
                       int K, int N) {
    const float* A =
        (ASEL == SEL_XIN)    ? g_xin :
        (ASEL == SEL_X)      ? g_x :
        (ASEL == SEL_STHAT)  ? g_sthat :
        (ASEL == SEL_CAT768) ? g_cat768 : Aext;
    float* C =
        (CSEL == SEL_X)      ? g_x :
        (CSEL == SEL_GATES)  ? g_gates :
        (CSEL == SEL_DECFEA) ? g_decfea : g_outvec;

    const int tid = threadIdx.x;
    const int tr = tid >> 4;          // 0..15 -> m group
    const int tc = tid & 15;          // 0..15 -> n group
    const int n0blk = blockIdx.x * 64;
    __shared__ float As[32 * 65];     // [kk][m]
    __shared__ float Ws[32 * 65];     // [kk][n]
    float accv[4][4];
    #pragma unroll
    for (int i = 0; i < 4; i++)
        #pragma unroll
        for (int j = 0; j < 4; j++) accv[i][j] = 0.f;

    for (int k0 = 0; k0 < K; k0 += 32) {
        for (int i = tid; i < 64*32; i += 256) {
            int m = i >> 5, kk = i & 31;
            As[kk*65 + m] = A[m*K + k0 + kk];
        }
        for (int i = tid; i < 64*32; i += 256) {
            int n = i >> 5, kk = i & 31;
            int ng = n0blk + n;
            Ws[kk*65 + n] = (ng < N) ? W[(size_t)ng*K + k0 + kk] : 0.f;
        }
        __syncthreads();
        #pragma unroll
        for (int kk = 0; kk < 32; kk++) {
            float a[4], w[4];
            #pragma unroll
            for (int i = 0; i < 4; i++) a[i] = As[kk*65 + tr*4 + i];
            #pragma unroll
            for (int j = 0; j < 4; j++) w[j] = Ws[kk*65 + tc*4 + j];
            #pragma unroll
            for (int i = 0; i < 4; i++)
                #pragma unroll
                for (int j = 0; j < 4; j++) accv[i][j] = fmaf(a[i], w[j], accv[i][j]);
        }
        __syncthreads();
    }
    #pragma unroll
    for (int i = 0; i < 4; i++) {
        int m = tr*4 + i;
        #pragma unroll
        for (int j = 0; j < 4; j++) {
            int ng = n0blk + tc*4 + j;
            if (ng < N) {
                float v = accv[i][j];
                if (b1) v += b1[ng];
                if (b2) v += b2[ng];
                if (ACC) C[m*N + ng] += v;
                else     C[m*N + ng]  = v;
            }
        }
    }
}

// ---------------- K3: LSTM cell elementwise ----------------
__global__ void __launch_bounds__(H) lstm_kernel(const float* __restrict__ c0) {
    int b = blockIdx.x, h = threadIdx.x;
    const float* g = g_gates + b*4*H;
    float ig = fsig(g[h]);
    float fg = fsig(g[H + h]);
    float gg = ftanh(g[2*H + h]);
    float og = fsig(g[3*H + h]);
    float cs = fg * c0[b*H + h] + ig * gg;
    float hs = og * ftanh(cs);
    g_sthat[b*H2 + h]       = hs;
    g_sthat[b*H2 + H + h]   = cs;
}

// ---------------- K5: attention scores (52 MB stream) ----------------
__global__ void __launch_bounds__(256) attn_scores_kernel(const float* __restrict__ ef,
                                   const float* __restrict__ Wv) {
    int warp = (blockIdx.x * blockDim.x + threadIdx.x) >> 5;
    int lane = threadIdx.x & 31;
    if (warp >= B*T) return;
    int b = warp / T;
    const float4* e4 = (const float4*)(ef + (size_t)warp * H2);
    const float4* d4 = (const float4*)(g_decfea + b * H2);
    const float4* w4 = (const float4*)Wv;
    float acc = 0.f;
    #pragma unroll
    for (int i = 0; i < 4; i++) {
        int p = i*32 + lane;
        float4 a = e4[p], d = d4[p], w = w4[p];
        acc += ftanh(a.x + d.x) * w.x;
        acc += ftanh(a.y + d.y) * w.y;
        acc += ftanh(a.z + d.z) * w.z;
        acc += ftanh(a.w + d.w) * w.w;
    }
    #pragma unroll
    for (int s = 16; s > 0; s >>= 1) acc += __shfl_xor_sync(0xFFFFFFFFu, acc, s);
    if (lane == 0) g_scores[warp] = acc;
}

// ---------------- K6: softmax over T + mask/renorm/stmt; zero g_ct/g_rowsum ----------------
__global__ void __launch_bounds__(256) softmaxT_kernel(const float* __restrict__ mask,
                                const float* __restrict__ stmt) {
    int b = blockIdx.x, tid = threadIdx.x;
    __shared__ float red[256];
    bool v0 = tid < T;
    bool v1 = (tid + 256) < T;
    float s0 = v0 ? g_scores[b*T + tid]       : -1e30f;
    float s1 = v1 ? g_scores[b*T + tid + 256] : -1e30f;

    // max
    red[tid] = fmaxf(s0, s1); __syncthreads();
    for (int s = 128; s > 0; s >>= 1) { if (tid < s) red[tid] = fmaxf(red[tid], red[tid+s]); __syncthreads(); }
    float M = red[0]; __syncthreads();

    float e0 = v0 ? __expf(s0 - M) : 0.f;
    float e1 = v1 ? __expf(s1 - M) : 0.f;
    red[tid] = e0 + e1; __syncthreads();
    for (int s = 128; s > 0; s >>= 1) { if (tid < s) red[tid] += red[tid+s]; __syncthreads(); }
    float S = red[0]; __syncthreads();

    float m0 = v0 ? mask[b*T + tid]       : 0.f;
    float m1 = v1 ? mask[b*T + tid + 256] : 0.f;
    float a0 = __fdividef(e0, S) * m0;
    float a1 = __fdividef(e1, S) * m1;
    red[tid] = a0 + a1; __syncthreads();
    for (int s = 128; s > 0; s >>= 1) { if (tid < s) red[tid] += red[tid+s]; __syncthreads(); }
    float S2 = red[0]; __syncthreads();

    if (v0) g_attn[b*T + tid]       = __fdividef(a0, S2) + (stmt[b*T + tid]       * m0);
    if (v1) g_attn[b*T + tid + 256] = __fdividef(a1, S2) + (stmt[b*T + tid + 256] * m1);

    // zero c_t accumulator and rowsum
    g_ct[b*H2 + tid]       = 0.f;
    g_ct[b*H2 + tid + 256] = 0.f;
    if (tid == 0) g_rowsum[b] = 0.f;
}

// ---------------- K7: c_t = attn @ encoder_outputs (52 MB stream) ----------------
__global__ void __launch_bounds__(256) ct_kernel(const float* __restrict__ eo) {
    int b = blockIdx.x, z = blockIdx.y;   // z in 0..7, 50 timesteps each
    int tid = threadIdx.x;
    __shared__ float sa[50];
    if (tid < 50) sa[tid] = g_attn[b*T + z*50 + tid];
    __syncthreads();
    const float* base = eo + ((size_t)b*T + z*50) * H2;
    float acc0 = 0.f, acc1 = 0.f;
    #pragma unroll 5
    for (int t = 0; t < 50; t++) {
        float a = sa[t];
        acc0 = fmaf(a, base[t*H2 + tid],       acc0);
        acc1 = fmaf(a, base[t*H2 + tid + 256], acc1);
    }
    atomicAdd(&g_ct[b*H2 + tid],       acc0);
    atomicAdd(&g_ct[b*H2 + tid + 256], acc1);
}

// ---------------- K8a: concat buffers ----------------
__global__ void __launch_bounds__(256) cats_kernel() {
    int b = blockIdx.x;
    for (int k = threadIdx.x; k < 1152; k += blockDim.x) {
        float v;
        if (k < 512)       v = g_ct[b*H2 + k];
        else if (k < 1024) v = g_sthat[b*H2 + (k - 512)];
        else               v = g_x[b*E + (k - 1024)];
        g_cat1152[b*1152 + k] = v;
    }
    for (int k = threadIdx.x; k < 768; k += blockDim.x) {
        float v = (k < 256) ? g_sthat[b*H2 + k] : g_ct[b*H2 + (k - 256)];
        g_cat768[b*768 + k] = v;
    }
}

// ---------------- K8b: p_gen ----------------
__global__ void __launch_bounds__(128) pgen_kernel(const float* __restrict__ Wpg,
                                                   const float* __restrict__ bpg) {
    int b = blockIdx.x, tid = threadIdx.x;
    __shared__ float red[128];
    float acc = 0.f;
    for (int k = tid; k < 1152; k += 128)
        acc = fmaf(g_cat1152[b*1152 + k], Wpg[k], acc);
    red[tid] = acc; __syncthreads();
    for (int s = 64; s > 0; s >>= 1) { if (tid < s) red[tid] += red[tid+s]; __syncthreads(); }
    if (tid == 0) g_pgen[b] = fsig(red[0] + bpg[0]);
}

// ---------------- K10: vocab GEMM + exp + rowsum (51 MB stream) ----------------
// BN=128 cols per block, 256 threads, 4x8 microtile. K = 256.
__global__ void __launch_bounds__(256) vocab_kernel(const float* __restrict__ Wo2,
                             const float* __restrict__ bo2,
                             float* __restrict__ outF) {
    const int tid = threadIdx.x;
    const int tr = tid >> 4;          // 0..15
    const int tc = tid & 15;          // 0..15
    const int n0blk = blockIdx.x * 128;
    __shared__ float As[32 * 65];     // [kk][m]
    __shared__ float Ws[32 * 129];    // [kk][n]
    __shared__ float srow[B];
    float accv[4][8];
    #pragma unroll
    for (int i = 0; i < 4; i++)
        #pragma unroll
        for (int j = 0; j < 8; j++) accv[i][j] = 0.f;

    for (int k0 = 0; k0 < H; k0 += 32) {
        for (int i = tid; i < 64*32; i += 256) {
            int m = i >> 5, kk = i & 31;
            As[kk*65 + m] = g_outvec[m*H + k0 + kk];
        }
        for (int i = tid; i < 128*32; i += 256) {
            int n = i >> 5, kk = i & 31;
            int ng = n0blk + n;
            Ws[kk*129 + n] = (ng < V) ? Wo2[(size_t)ng*H + k0 + kk] : 0.f;
        }
        __syncthreads();
        #pragma unroll
        for (int kk = 0; kk < 32; kk++) {
            float a[4], w[8];
            #pragma unroll
            for (int i = 0; i < 4; i++) a[i] = As[kk*65 + tr*4 + i];
            #pragma unroll
            for (int j = 0; j < 8; j++) w[j] = Ws[kk*129 + tc*8 + j];
            #pragma unroll
            for (int i = 0; i < 4; i++)
                #pragma unroll
                for (int j = 0; j < 8; j++) accv[i][j] = fmaf(a[i], w[j], accv[i][j]);
        }
        __syncthreads();
    }

    if (tid < B) srow[tid] = 0.f;
    __syncthreads();
    #pragma unroll
    for (int i = 0; i < 4; i++) {
        int m = tr*4 + i;
        float rs = 0.f;
        #pragma unroll
        for (int j = 0; j < 8; j++) {
            int ng = n0blk + tc*8 + j;
            if (ng < V) {
                float e = __expf(accv[i][j] + bo2[ng]);
                outF[(size_t)m*VX + ng] = e;
                rs += e;
            }
        }
        atomicAdd(&srow[m], rs);
    }
    __syncthreads();
    if (tid < B) atomicAdd(&g_rowsum[tid], srow[tid]);
}

// ---------------- K10b: scale = pgen / rowsum ----------------
__global__ void __launch_bounds__(64) scale_kernel() {
    int t = threadIdx.x;
    if (t < B) g_scale[t] = g_pgen[t] / g_rowsum[t];
}

// ---------------- K11a: normalize + extras + aux-output copies ----------------
__global__ void __launch_bounds__(256) finalize_kernel(float* __restrict__ out,
                                const float* __restrict__ extra,
                                const float* __restrict__ cov,
                                int full) {
    const int totalV = B * VX;
    const int extraN = full ? (B*H + B*H + B*H2 + B*T + B + B*T) : 0;
    const int total  = totalV + extraN;
    for (int idx = blockIdx.x * blockDim.x + threadIdx.x; idx < total;
         idx += gridDim.x * blockDim.x) {
        if (idx < totalV) {
            int b = idx / VX;
            int v = idx - b * VX;
            if (v < V) out[idx] = out[idx] * g_scale[b];
            else       out[idx] = extra[b*X + (v - V)];
        } else {
            int r = idx - totalV;
            if (r < B*H) {                                   // h_s
                int b = r / H, h = r - b*H;
                out[OFF_HS + r] = g_sthat[b*H2 + h];
            } else if ((r -= B*H) < B*H) {                   // c_s
                int b = r / H, h = r - b*H;
                out[OFF_CS + r] = g_sthat[b*H2 + H + h];
            } else if ((r -= B*H) < B*H2) {                  // c_t
                out[OFF_CT + r] = g_ct[r];
            } else if ((r -= B*H2) < B*T) {                  // attn
                out[OFF_ATTN + r] = g_attn[r];
            } else if ((r -= B*T) < B) {                     // p_gen
                out[OFF_PGEN + r] = g_pgen[r];
            } else {                                         // coverage
                r -= B;
                out[OFF_COV + r] = cov[r];
            }
        }
    }
}

// ---------------- K11b: pointer scatter ----------------
__global__ void __launch_bounds__(256) scatter_kernel(float* __restrict__ out,
                                                      const int* __restrict__ ebev) {
    int idx = blockIdx.x * blockDim.x + threadIdx.x;
    if (idx >= B*T) return;
    int b = idx / T;
    float v = (1.f - g_pgen[b]) * g_attn[idx];
    int col = ebev[idx];
    atomicAdd(&out[(size_t)b*VX + col], v);
}

// ---------------- host launcher ----------------
extern "C" void kernel_launch(void* const* d_in, const int* in_sizes, int n_in,
                              void* d_out, int out_size) {
    const int*   y     = (const int*)  d_in[0];
    const float* h0    = (const float*)d_in[1];
    // d_in[2] = c0 (used below)
    const float* c0    = (const float*)d_in[2];
    const float* eo    = (const float*)d_in[3];
    const float* ef    = (const float*)d_in[4];
    const float* stmt  = (const float*)d_in[5];
    const float* mask  = (const float*)d_in[6];
    const float* ct1   = (const float*)d_in[7];
    const float* extra = (const float*)d_in[8];
    const int*   ebev  = (const int*)  d_in[9];
    const float* cov   = (const float*)d_in[10];
    // optional "step" scalar at index 11
    int p = (n_in > 11 && in_sizes[11] == 1) ? 12 : 11;
    const float* emb  = (const float*)d_in[p+0];
    const float* Wxc  = (const float*)d_in[p+1];
    const float* bxc  = (const float*)d_in[p+2];
    const float* W_ih = (const float*)d_in[p+3];
    const float* W_hh = (const float*)d_in[p+4];
    const float* b_ih = (const float*)d_in[p+5];
    const float* b_hh = (const float*)d_in[p+6];
    const float* Wdp  = (const float*)d_in[p+7];
    const float* bdp  = (const float*)d_in[p+8];
    const float* Wv   = (const float*)d_in[p+9];
    const float* Wpg  = (const float*)d_in[p+10];
    const float* bpg  = (const float*)d_in[p+11];
    const float* Wo1  = (const float*)d_in[p+12];
    const float* bo1  = (const float*)d_in[p+13];
    const float* Wo2  = (const float*)d_in[p+14];
    const float* bo2  = (const float*)d_in[p+15];
    float* out = (float*)d_out;
    int full = (out_size >= OUT_TOTAL) ? 1 : 0;

    // 1. x = [c_t_1 | emb[y]] @ Wxc^T + bxc
    xin_kernel<<<B, 128>>>(y, ct1, emb);
    gemm64<SEL_XIN, SEL_X, 0><<<(E + 63)/64, 256>>>(nullptr, Wxc, bxc, nullptr, 640, E);

    // 2. LSTM gates = x @ W_ih^T + h0 @ W_hh^T + b_ih + b_hh
    gemm64<SEL_X, SEL_GATES, 0><<<(4*H + 63)/64, 256>>>(nullptr, W_ih, b_ih, b_hh, E, 4*H);
    gemm64<SEL_EXT, SEL_GATES, 1><<<(4*H + 63)/64, 256>>>(h0, W_hh, nullptr, nullptr, H, 4*H);
    lstm_kernel<<<B, H>>>(c0);

    // 3. dec_fea = s_t_hat @ Wdp^T + bdp
    gemm64<SEL_STHAT, SEL_DECFEA, 0><<<(H2 + 63)/64, 256>>>(nullptr, Wdp, bdp, nullptr, H2, H2);

    // 4. attention
    attn_scores_kernel<<<(B*T + 7)/8, 256>>>(ef, Wv);
    softmaxT_kernel<<<B, 256>>>(mask, stmt);
    ct_kernel<<<dim3(B, 8), 256>>>(eo);

    // 5. p_gen and output head
    cats_kernel<<<B, 256>>>();
    pgen_kernel<<<B, 128>>>(Wpg, bpg);
    gemm64<SEL_CAT768, SEL_OUTVEC, 0><<<(H + 63)/64, 256>>>(nullptr, Wo1, bo1, nullptr, 768, H);

    // 6. vocab distribution
    vocab_kernel<<<(V + 127)/128, 256>>>(Wo2, bo2, out);
    scale_kernel<<<1, 64>>>();
    finalize_kernel<<<1024, 256>>>(out, extra, cov, full);
    scatter_kernel<<<(B*T + 255)/256, 256>>>(out, ebev);
}

// round 5
// speedup vs baseline: 2.0993x; 2.0795x over previous
#include <cuda_runtime.h>
#include <cuda_bf16.h>
#include <cstdint>

#define B   64
#define T   400
#define H   256
#define E   128
#define V   50000
#define X   500
#define H2  512
#define VX  50500

#define OFF_HS    (B*VX)
#define OFF_CS    (OFF_HS + B*H)
#define OFF_CT    (OFF_CS + B*H)
#define OFF_ATTN  (OFF_CT + B*H2)
#define OFF_PGEN  (OFF_ATTN + B*T)
#define OFF_COV   (OFF_PGEN + B)
#define OUT_TOTAL (OFF_COV + B*T)

__device__ __align__(16) float g_x[B*E];
__device__ __align__(16) float g_gates[B*4*H];
__device__ __align__(16) float g_sthat[B*H2];   // [h_s | c_s]
__device__ __align__(16) float g_decfea[B*H2];
__device__ __align__(16) float g_scores[B*T];
__device__ __align__(16) float g_attn[B*T];
__device__ __align__(16) float g_ct[B*H2];
__device__ __align__(16) float g_outvec[B*H];
__device__ float g_rowsum[B];
__device__ float g_pgen[B];

__device__ __forceinline__ void ffma2(unsigned long long& a,
                                      unsigned long long x, unsigned long long y) {
    asm("fma.rn.f32x2 %0, %1, %2, %0;" : "+l"(a) : "l"(x), "l"(y));
}
__device__ __forceinline__ float hsum2(unsigned long long v) {
    float lo, hi;
    asm("mov.b64 {%0,%1}, %2;" : "=f"(lo), "=f"(hi) : "l"(v));
    return lo + hi;
}
__device__ __forceinline__ float ftanh(float x) {
    x = fminf(fmaxf(x, -15.f), 15.f);
    float e = __expf(2.f * x);
    return __fdividef(e - 1.f, e + 1.f);
}
__device__ __forceinline__ float tanha(float x) {
    float r; asm("tanh.approx.f32 %0, %1;" : "=f"(r) : "f"(x)); return r;
}
__device__ __forceinline__ float fsig(float x) {
    return __fdividef(1.f, 1.f + __expf(-x));
}

// ---- K0: zero accumulators, pre-load biases (no dependencies) ----
__global__ void __launch_bounds__(256) init_kernel(
    const float* __restrict__ bxc, const float* __restrict__ b_ih,
    const float* __restrict__ b_hh, const float* __restrict__ bdp,
    const float* __restrict__ bo1) {
    const int S0 = B*H2, S1 = S0 + B, S2 = S1 + B*E, S3 = S2 + B*4*H,
              S4 = S3 + B*H2, S5 = S4 + B*H;
    int stride = gridDim.x * blockDim.x;
    for (int i = blockIdx.x * blockDim.x + threadIdx.x; i < S5; i += stride) {
        if (i < S0)      g_ct[i] = 0.f;
        else if (i < S1) g_rowsum[i - S0] = 0.f;
        else if (i < S2) { int r = i - S1; g_x[r]      = bxc[r & 127]; }
        else if (i < S3) { int r = i - S2; g_gates[r]  = b_ih[r & 1023] + b_hh[r & 1023]; }
        else if (i < S4) { int r = i - S3; g_decfea[r] = bdp[r & 511]; }
        else             { int r = i - S4; g_outvec[r] = bo1[r & 255]; }
    }
}

// ---- templated small GEMM: C[64,N] += A_slice[64,128] @ W_slice[N,128]^T ----
// grid = (N/16, nSlices); block = 256. A in smem [kq][m] float4; W broadcast LDG.
#define OP_X      0
#define OP_GATES  1
#define OP_DECFEA 2
#define OP_OUT    3

template<int OP>
__global__ void __launch_bounds__(256) smallmm(
    const float* __restrict__ eA, const float* __restrict__ emb,
    const int* __restrict__ y,
    const float* __restrict__ W1, const float* __restrict__ W2) {
    constexpr int N = (OP==OP_X) ? 128 : (OP==OP_GATES) ? 1024 :
                      (OP==OP_DECFEA) ? 512 : 256;
    __shared__ float4 As4[32*65];
    const int tid   = threadIdx.x;
    const int slice = blockIdx.y;
    const int n0    = blockIdx.x * 16;

    const float* Ap = nullptr; int lda = 0;
    const float* Wp = nullptr; int ldw = 0;
    bool gather = false;
    if (OP == OP_X) {                      // A = [c_t_1 | emb[y]], K=640
        if (slice < 4) { Ap = eA + slice*128; lda = 512; } else gather = true;
        Wp = W1 + slice*128; ldw = 640;
    } else if (OP == OP_GATES) {           // slice0: x@W_ih; slices1-2: h0@W_hh
        if (slice == 0) { Ap = g_x; lda = 128; Wp = W1; ldw = 128; }
        else { Ap = eA + (slice-1)*128; lda = 256; Wp = W2 + (slice-1)*128; ldw = 256; }
    } else if (OP == OP_DECFEA) {          // s_t_hat @ Wdp, K=512
        Ap = g_sthat + slice*128; lda = 512; Wp = W1 + slice*128; ldw = 512;
    } else {                               // [h_s | c_t] @ Wo1, K=768
        Ap = (slice < 2) ? (g_sthat + slice*128) : (g_ct + (slice-2)*128); lda = 512;
        Wp = W1 + slice*128; ldw = 768;
    }
    float* C = (OP==OP_X) ? g_x : (OP==OP_GATES) ? g_gates :
               (OP==OP_DECFEA) ? g_decfea : g_outvec;

    for (int i = tid; i < 64*32; i += 256) {
        int m = i >> 5, kq = i & 31;
        float4 v;
        if (OP == OP_X && gather) v = ((const float4*)(emb + (size_t)y[m]*128))[kq];
        else                      v = ((const float4*)(Ap + m*lda))[kq];
        As4[kq*65 + m] = v;
    }
    __syncthreads();

    const int lane = tid & 31, wp = tid >> 5;
    const float* Wr0 = Wp + (size_t)(n0 + wp*2 + 0) * ldw;
    const float* Wr1 = Wp + (size_t)(n0 + wp*2 + 1) * ldw;
    unsigned long long a00 = 0, a01 = 0, a10 = 0, a11 = 0;
    #pragma unroll 8
    for (int kq = 0; kq < 32; kq++) {
        ulonglong2 v0 = *(const ulonglong2*)&As4[kq*65 + lane];
        ulonglong2 v1 = *(const ulonglong2*)&As4[kq*65 + lane + 32];
        ulonglong2 w0 = *(const ulonglong2*)(Wr0 + 4*kq);
        ulonglong2 w1 = *(const ulonglong2*)(Wr1 + 4*kq);
        ffma2(a00, v0.x, w0.x); ffma2(a00, v0.y, w0.y);
        ffma2(a01, v1.x, w0.x); ffma2(a01, v1.y, w0.y);
        ffma2(a10, v0.x, w1.x); ffma2(a10, v0.y, w1.y);
        ffma2(a11, v1.x, w1.x); ffma2(a11, v1.y, w1.y);
    }
    int c0 = n0 + wp*2;
    atomicAdd(&C[lane*N + c0],          hsum2(a00));
    atomicAdd(&C[(lane+32)*N + c0],     hsum2(a01));
    atomicAdd(&C[lane*N + c0 + 1],      hsum2(a10));
    atomicAdd(&C[(lane+32)*N + c0 + 1], hsum2(a11));
}

// ---- LSTM cell ----
__global__ void __launch_bounds__(H) lstm_kernel(const float* __restrict__ c0) {
    int b = blockIdx.x, h = threadIdx.x;
    const float* g = g_gates + b*4*H;
    float ig = fsig(g[h]);
    float fg = fsig(g[H + h]);
    float gg = ftanh(g[2*H + h]);
    float og = fsig(g[3*H + h]);
    float cs = fg * c0[b*H + h] + ig * gg;
    float hs = og * ftanh(cs);
    g_sthat[b*H2 + h]     = hs;
    g_sthat[b*H2 + H + h] = cs;
}

// ---- attention scores (52 MB stream) ----
__global__ void __launch_bounds__(256) attn_scores_kernel(
    const float* __restrict__ ef, const float* __restrict__ Wv) {
    int warp = (blockIdx.x * blockDim.x + threadIdx.x) >> 5;
    int lane = threadIdx.x & 31;
    if (warp >= B*T) return;
    int b = warp / T;
    const float4* e4 = (const float4*)(ef + (size_t)warp * H2);
    const float4* d4 = (const float4*)(g_decfea + b * H2);
    const float4* w4 = (const float4*)Wv;
    float acc = 0.f;
    #pragma unroll
    for (int i = 0; i < 4; i++) {
        int p = i*32 + lane;
        float4 a = e4[p], d = d4[p], w = w4[p];
        acc += tanha(a.x + d.x) * w.x;
        acc += tanha(a.y + d.y) * w.y;
        acc += tanha(a.z + d.z) * w.z;
        acc += tanha(a.w + d.w) * w.w;
    }
    #pragma unroll
    for (int s = 16; s > 0; s >>= 1) acc += __shfl_xor_sync(0xFFFFFFFFu, acc, s);
    if (lane == 0) g_scores[warp] = acc;
}

// ---- softmax over T + mask/renorm/stmt ----
__global__ void __launch_bounds__(256) softmaxT_kernel(
    const float* __restrict__ mask, const float* __restrict__ stmt) {
    int b = blockIdx.x, tid = threadIdx.x;
    __shared__ float red[256];
    bool v0 = tid < T, v1 = (tid + 256) < T;
    float s0 = v0 ? g_scores[b*T + tid]       : -1e30f;
    float s1 = v1 ? g_scores[b*T + tid + 256] : -1e30f;

    red[tid] = fmaxf(s0, s1); __syncthreads();
    for (int s = 128; s > 0; s >>= 1) { if (tid < s) red[tid] = fmaxf(red[tid], red[tid+s]); __syncthreads(); }
    float M = red[0]; __syncthreads();

    float e0 = v0 ? __expf(s0 - M) : 0.f;
    float e1 = v1 ? __expf(s1 - M) : 0.f;
    red[tid] = e0 + e1; __syncthreads();
    for (int s = 128; s > 0; s >>= 1) { if (tid < s) red[tid] += red[tid+s]; __syncthreads(); }
    float S = red[0]; __syncthreads();

    float m0 = v0 ? mask[b*T + tid]       : 0.f;
    float m1 = v1 ? mask[b*T + tid + 256] : 0.f;
    float a0 = __fdividef(e0, S) * m0;
    float a1 = __fdividef(e1, S) * m1;
    red[tid] = a0 + a1; __syncthreads();
    for (int s = 128; s > 0; s >>= 1) { if (tid < s) red[tid] += red[tid+s]; __syncthreads(); }
    float S2 = red[0]; __syncthreads();

    if (v0) g_attn[b*T + tid]       = __fdividef(a0, S2) + stmt[b*T + tid]       * m0;
    if (v1) g_attn[b*T + tid + 256] = __fdividef(a1, S2) + stmt[b*T + tid + 256] * m1;
}

// ---- c_t = attn @ encoder_outputs (52 MB stream) ----
__global__ void __launch_bounds__(256) ct_kernel(const float* __restrict__ eo) {
    int b = blockIdx.x, z = blockIdx.y, tid = threadIdx.x;
    __shared__ float sa[50];
    if (tid < 50) sa[tid] = g_attn[b*T + z*50 + tid];
    __syncthreads();
    const float* base = eo + ((size_t)b*T + z*50) * H2;
    float acc0 = 0.f, acc1 = 0.f;
    #pragma unroll 5
    for (int t = 0; t < 50; t++) {
        float a = sa[t];
        acc0 = fmaf(a, base[t*H2 + tid],       acc0);
        acc1 = fmaf(a, base[t*H2 + tid + 256], acc1);
    }
    atomicAdd(&g_ct[b*H2 + tid],       acc0);
    atomicAdd(&g_ct[b*H2 + tid + 256], acc1);
}

// ---- p_gen: reads [c_t | s_t_hat | x] directly ----
__global__ void __launch_bounds__(128) pgen_kernel(
    const float* __restrict__ Wpg, const float* __restrict__ bpg) {
    int b = blockIdx.x, tid = threadIdx.x;
    __shared__ float red[128];
    float acc = 0.f;
    for (int k = tid; k < 1152; k += 128) {
        float v = (k < 512) ? g_ct[b*H2 + k]
               : (k < 1024) ? g_sthat[b*H2 + (k - 512)]
               :              g_x[b*E + (k - 1024)];
        acc = fmaf(v, Wpg[k], acc);
    }
    red[tid] = acc; __syncthreads();
    for (int s = 64; s > 0; s >>= 1) { if (tid < s) red[tid] += red[tid+s]; __syncthreads(); }
    if (tid == 0) g_pgen[b] = fsig(red[0] + bpg[0]);
}

// ---- vocab GEMM + exp + rowsum (FFMA2; 50 MB W stream) ----
__global__ void __launch_bounds__(256) vocab_kernel(
    const float* __restrict__ Wo2, const float* __restrict__ bo2,
    float* __restrict__ outF) {
    extern __shared__ float4 dsm[];            // [kq 0..63][m 0..63], stride 65
    __shared__ float srow[64];
    const int tid = threadIdx.x;
    const int n0  = blockIdx.x * 64;

    for (int i = tid; i < 64*64; i += 256) {
        int m = i >> 6, kq = i & 63;
        dsm[kq*65 + m] = ((const float4*)g_outvec)[m*64 + kq];
    }
    if (tid < 64) srow[tid] = 0.f;
    __syncthreads();

    const int lane = tid & 31, wp = tid >> 5;
    const float* Wr[8];
    #pragma unroll
    for (int c = 0; c < 8; c++) {
        int n = n0 + wp*8 + c; if (n >= V) n = V - 1;
        Wr[c] = Wo2 + (size_t)n * 256;
    }
    unsigned long long acc[8][2];
    #pragma unroll
    for (int c = 0; c < 8; c++) { acc[c][0] = 0ull; acc[c][1] = 0ull; }

    #pragma unroll 4
    for (int kq = 0; kq < 64; kq++) {
        ulonglong2 a0 = *(const ulonglong2*)&dsm[kq*65 + lane];
        ulonglong2 a1 = *(const ulonglong2*)&dsm[kq*65 + lane + 32];
        #pragma unroll
        for (int c = 0; c < 8; c++) {
            ulonglong2 wv = *(const ulonglong2*)(Wr[c] + 4*kq);
            ffma2(acc[c][0], a0.x, wv.x); ffma2(acc[c][0], a0.y, wv.y);
            ffma2(acc[c][1], a1.x, wv.x); ffma2(acc[c][1], a1.y, wv.y);
        }
    }
    __syncthreads();
    float* sOut = (float*)dsm;                 // reuse: [m 0..63][cc 0..63], stride 65
    #pragma unroll
    for (int c = 0; c < 8; c++) {
        sOut[lane*65 + wp*8 + c]      = hsum2(acc[c][0]);
        sOut[(lane+32)*65 + wp*8 + c] = hsum2(acc[c][1]);
    }
    __syncthreads();
    #pragma unroll 1
    for (int j = 0; j < 16; j++) {
        int i = tid + j*256;
        int m = i >> 6, cc = i & 63;
        int n = n0 + cc;
        float e = 0.f;
        if (n < V) {
            e = __expf(sOut[m*65 + cc] + bo2[n]);
            outF[(size_t)m*VX + n] = e;
        }
        float s = e;
        #pragma unroll
        for (int o = 16; o; o >>= 1) s += __shfl_xor_sync(0xFFFFFFFFu, s, o);
        if (lane == 0) atomicAdd(&srow[m], s);
    }
    __syncthreads();
    if (tid < 64) atomicAdd(&g_rowsum[tid], srow[tid]);
}

// ---- finalize: scale + extras + aux copies ----
__global__ void __launch_bounds__(256) finalize_kernel(
    float* __restrict__ out, const float* __restrict__ extra,
    const float* __restrict__ cov, int full) {
    const int totalV = B * VX;
    const int extraN = full ? (B*H + B*H + B*H2 + B*T + B + B*T) : 0;
    const int total  = totalV + extraN;
    for (int idx = blockIdx.x * blockDim.x + threadIdx.x; idx < total;
         idx += gridDim.x * blockDim.x) {
        if (idx < totalV) {
            int b = idx / VX;
            int v = idx - b * VX;
            if (v < V) out[idx] = out[idx] * __fdividef(g_pgen[b], g_rowsum[b]);
            else       out[idx] = extra[b*X + (v - V)];
        } else {
            int r = idx - totalV;
            if (r < B*H) {
                int b = r / H, h = r - b*H;
                out[OFF_HS + r] = g_sthat[b*H2 + h];
            } else if ((r -= B*H) < B*H) {
                int b = r / H, h = r - b*H;
                out[OFF_CS + r] = g_sthat[b*H2 + H + h];
            } else if ((r -= B*H) < B*H2) {
                out[OFF_CT + r] = g_ct[r];
            } else if ((r -= B*H2) < B*T) {
                out[OFF_ATTN + r] = g_attn[r];
            } else if ((r -= B*T) < B) {
                out[OFF_PGEN + r] = g_pgen[r];
            } else {
                r -= B;
                out[OFF_COV + r] = cov[r];
            }
        }
    }
}

// ---- pointer scatter ----
__global__ void __launch_bounds__(256) scatter_kernel(
    float* __restrict__ out, const int* __restrict__ ebev) {
    int idx = blockIdx.x * blockDim.x + threadIdx.x;
    if (idx >= B*T) return;
    int b = idx / T;
    float v = (1.f - g_pgen[b]) * g_attn[idx];
    atomicAdd(&out[(size_t)b*VX + ebev[idx]], v);
}

// ---- host launcher ----
extern "C" void kernel_launch(void* const* d_in, const int* in_sizes, int n_in,
                              void* d_out, int out_size) {
    const int*   y     = (const int*)  d_in[0];
    const float* h0    = (const float*)d_in[1];
    const float* c0    = (const float*)d_in[2];
    const float* eo    = (const float*)d_in[3];
    const float* ef    = (const float*)d_in[4];
    const float* stmt  = (const float*)d_in[5];
    const float* mask  = (const float*)d_in[6];
    const float* ct1   = (const float*)d_in[7];
    const float* extra = (const float*)d_in[8];
    const int*   ebev  = (const int*)  d_in[9];
    const float* cov   = (const float*)d_in[10];
    int p = (n_in > 11 && in_sizes[11] == 1) ? 12 : 11;
    const float* emb  = (const float*)d_in[p+0];
    const float* Wxc  = (const float*)d_in[p+1];
    const float* bxc  = (const float*)d_in[p+2];
    const float* W_ih = (const float*)d_in[p+3];
    const float* W_hh = (const float*)d_in[p+4];
    const float* b_ih = (const float*)d_in[p+5];
    const float* b_hh = (const float*)d_in[p+6];
    const float* Wdp  = (const float*)d_in[p+7];
    const float* bdp  = (const float*)d_in[p+8];
    const float* Wv   = (const float*)d_in[p+9];
    const float* Wpg  = (const float*)d_in[p+10];
    const float* bpg  = (const float*)d_in[p+11];
    const float* Wo1  = (const float*)d_in[p+12];
    const float* bo1  = (const float*)d_in[p+13];
    const float* Wo2  = (const float*)d_in[p+14];
    const float* bo2  = (const float*)d_in[p+15];
    float* out = (float*)d_out;
    int full = (out_size >= OUT_TOTAL) ? 1 : 0;

    const int VOC_SMEM = 65*64*sizeof(float4);   // 66,560 B
    cudaFuncSetAttribute(vocab_kernel,
        cudaFuncAttributeMaxDynamicSharedMemorySize, VOC_SMEM);

    init_kernel<<<148, 256>>>(bxc, b_ih, b_hh, bdp, bo1);
    smallmm<OP_X>     <<<dim3(8, 5),  256>>>(ct1, emb, y, Wxc, nullptr);
    smallmm<OP_GATES> <<<dim3(64, 3), 256>>>(h0, nullptr, nullptr, W_ih, W_hh);
    lstm_kernel<<<B, H>>>(c0);
    smallmm<OP_DECFEA><<<dim3(32, 4), 256>>>(nullptr, nullptr, nullptr, Wdp, nullptr);
    attn_scores_kernel<<<(B*T + 7)/8, 256>>>(ef, Wv);
    softmaxT_kernel<<<B, 256>>>(mask, stmt);
    ct_kernel<<<dim3(B, 8), 256>>>(eo);
    pgen_kernel<<<B, 128>>>(Wpg, bpg);
    smallmm<OP_OUT>   <<<dim3(16, 6), 256>>>(nullptr, nullptr, nullptr, Wo1, nullptr);
    vocab_kernel<<<(V + 63)/64, 256, VOC_SMEM>>>(Wo2, bo2, out);
    finalize_kernel<<<1024, 256>>>(out, extra, cov, full);
    scatter_kernel<<<(B*T + 255)/256, 256>>>(out, ebev);
}